// round 1
// baseline (speedup 1.0000x reference)
#include <cuda_runtime.h>
#include <cstdint>

#define BB 4
#define TT 2048
#define CC 2048
#define FF 8192
#define BT (BB*TT)          // 8192
#define NCH 64
#define LCH 32               // NCH*LCH == TT

// ---------------- scratch (device globals; no allocation allowed) ----------
__device__ float g_xln [(size_t)BT*CC];
__device__ float g_k   [(size_t)BT*CC];
__device__ float g_v   [(size_t)BT*CC];
__device__ float g_r   [(size_t)BT*CC];
__device__ float g_xmid[(size_t)BT*CC];
__device__ float g_x2  [(size_t)BT*CC];
__device__ float g_H   [(size_t)BT*FF];
__device__ float g_dv  [(size_t)BT*CC];
__device__ float g_cr  [(size_t)BT*CC];
__device__ float g_Aloc[(size_t)BB*CC*NCH];
__device__ float g_Bloc[(size_t)BB*CC*NCH];
__device__ float g_Sa  [(size_t)BB*CC*NCH];
__device__ float g_Sb  [(size_t)BB*CC*NCH];

// ---------------- layernorm ------------------------------------------------
__device__ __forceinline__ void blockReduce2(float& a, float& b) {
    __shared__ float sa[8], sb[8];
    int lane = threadIdx.x & 31, w = threadIdx.x >> 5;
    #pragma unroll
    for (int o = 16; o > 0; o >>= 1) {
        a += __shfl_down_sync(0xffffffffu, a, o);
        b += __shfl_down_sync(0xffffffffu, b, o);
    }
    if (lane == 0) { sa[w] = a; sb[w] = b; }
    __syncthreads();
    if (w == 0) {
        a = (lane < 8) ? sa[lane] : 0.f;
        b = (lane < 8) ? sb[lane] : 0.f;
        #pragma unroll
        for (int o = 4; o > 0; o >>= 1) {
            a += __shfl_down_sync(0xffffffffu, a, o);
            b += __shfl_down_sync(0xffffffffu, b, o);
        }
        if (lane == 0) { sa[0] = a; sb[0] = b; }
    }
    __syncthreads();
    a = sa[0]; b = sb[0];
    __syncthreads();
}

__global__ __launch_bounds__(256) void ln_kernel(
    const float* __restrict__ x, const float* __restrict__ g,
    const float* __restrict__ bia, float* __restrict__ y)
{
    size_t row = blockIdx.x;
    const float* xr = x + row * CC;
    float* yr = y + row * CC;
    float s = 0.f, q = 0.f;
    for (int i = threadIdx.x; i < CC; i += 256) {
        float v = xr[i];
        s += v; q += v * v;
    }
    blockReduce2(s, q);
    float mu = s * (1.f / CC);
    float var = q * (1.f / CC) - mu * mu;
    float rstd = rsqrtf(var + 1e-5f);
    for (int i = threadIdx.x; i < CC; i += 256)
        yr[i] = (xr[i] - mu) * rstd * g[i] + bia[i];
}

// ---------------- GEMM: Y[M,N] = A[M,K] * W[N,K]^T --------------------------
// SHIFT: A-row m reads A row (m-1), zeros when (m % TT)==0 (time shift).
// EPI: 0 none, 1 relu^2, 2 sigmoid.
template <bool SHIFT, int EPI>
__global__ __launch_bounds__(256) void gemm_kernel(
    const float* __restrict__ A, const float* __restrict__ W,
    float* __restrict__ Y, int M, int N, int K)
{
    __shared__ float As[128][16];
    __shared__ float Bs[16][128];

    const int m0 = blockIdx.y * 128;
    const int n0 = blockIdx.x * 128;
    const int tid = threadIdx.x;
    const int tr = tid >> 4;        // 0..15
    const int tc = tid & 15;        // 0..15
    const int lRow = tid >> 2;      // 0..63
    const int lCol = (tid & 3) * 4; // 0,4,8,12

    float acc[8][8];
    #pragma unroll
    for (int i = 0; i < 8; i++)
        #pragma unroll
        for (int j = 0; j < 8; j++) acc[i][j] = 0.f;

    for (int k0 = 0; k0 < K; k0 += 16) {
        // load A tile (128 x 16)
        #pragma unroll
        for (int it = 0; it < 2; it++) {
            int ar = lRow + it * 64;
            int gm = m0 + ar;
            float4 f;
            if (SHIFT && ((gm & (TT - 1)) == 0)) {
                f = make_float4(0.f, 0.f, 0.f, 0.f);
            } else {
                int src = SHIFT ? (gm - 1) : gm;
                f = *(const float4*)&A[(size_t)src * K + k0 + lCol];
            }
            *(float4*)&As[ar][lCol] = f;
        }
        // load W tile (128 x 16) transposed into Bs[k][n]
        #pragma unroll
        for (int it = 0; it < 2; it++) {
            int br = lRow + it * 64;
            float4 f = *(const float4*)&W[(size_t)(n0 + br) * K + k0 + lCol];
            Bs[lCol + 0][br] = f.x;
            Bs[lCol + 1][br] = f.y;
            Bs[lCol + 2][br] = f.z;
            Bs[lCol + 3][br] = f.w;
        }
        __syncthreads();

        #pragma unroll
        for (int kk = 0; kk < 16; kk++) {
            float ra[8], rb[8];
            #pragma unroll
            for (int i = 0; i < 8; i++) ra[i] = As[tr * 8 + i][kk];
            *(float4*)&rb[0] = *(const float4*)&Bs[kk][tc * 8];
            *(float4*)&rb[4] = *(const float4*)&Bs[kk][tc * 8 + 4];
            #pragma unroll
            for (int i = 0; i < 8; i++)
                #pragma unroll
                for (int j = 0; j < 8; j++)
                    acc[i][j] = fmaf(ra[i], rb[j], acc[i][j]);
        }
        __syncthreads();
    }

    #pragma unroll
    for (int i = 0; i < 8; i++) {
        size_t gm = m0 + tr * 8 + i;
        #pragma unroll
        for (int j = 0; j < 8; j += 4) {
            float4 f;
            float e0 = acc[i][j], e1 = acc[i][j + 1], e2 = acc[i][j + 2], e3 = acc[i][j + 3];
            if (EPI == 1) {           // relu^2
                e0 = e0 > 0.f ? e0 * e0 : 0.f;
                e1 = e1 > 0.f ? e1 * e1 : 0.f;
                e2 = e2 > 0.f ? e2 * e2 : 0.f;
                e3 = e3 > 0.f ? e3 * e3 : 0.f;
            } else if (EPI == 2) {    // sigmoid
                e0 = 1.f / (1.f + __expf(-e0));
                e1 = 1.f / (1.f + __expf(-e1));
                e2 = 1.f / (1.f + __expf(-e2));
                e3 = 1.f / (1.f + __expf(-e3));
            }
            f.x = e0; f.y = e1; f.z = e2; f.w = e3;
            *(float4*)&Y[gm * N + n0 + tc * 8 + j] = f;
        }
    }
}

// ---------------- WKV chunked scan ------------------------------------------
__global__ __launch_bounds__(256) void wkv_passA(const float* __restrict__ td)
{
    int tid = blockIdx.x * 256 + threadIdx.x;   // BB*NCH*CC threads
    int c = tid % CC;
    int j = (tid / CC) % NCH;
    int b = tid / (CC * NCH);
    float e = __expf(td[c]);
    float d = __expf(-e);
    float a = 0.f, bb = 0.f;
    size_t base = ((size_t)b * TT + (size_t)j * LCH) * CC + c;
    #pragma unroll 4
    for (int t = 0; t < LCH; t++) {
        float ek = __expf(g_k[base + (size_t)t * CC]);
        a  = d * a  + ek * g_v[base + (size_t)t * CC];
        bb = d * bb + ek;
    }
    size_t idx = ((size_t)b * NCH + j) * CC + c;
    g_Aloc[idx] = a;
    g_Bloc[idx] = bb;
}

__global__ __launch_bounds__(256) void wkv_passB(const float* __restrict__ td)
{
    int tid = blockIdx.x * 256 + threadIdx.x;   // BB*CC threads
    int c = tid % CC;
    int b = tid / CC;
    float e = __expf(td[c]);
    float dL = __expf(-(float)LCH * e);
    float sa = 0.f, sb = 0.f;
    for (int j = 0; j < NCH; j++) {
        size_t idx = ((size_t)b * NCH + j) * CC + c;
        g_Sa[idx] = sa;
        g_Sb[idx] = sb;
        sa = dL * sa + g_Aloc[idx];
        sb = dL * sb + g_Bloc[idx];
    }
}

__global__ __launch_bounds__(256) void wkv_passC(
    const float* __restrict__ td, const float* __restrict__ x)
{
    int tid = blockIdx.x * 256 + threadIdx.x;
    int c = tid % CC;
    int j = (tid / CC) % NCH;
    int b = tid / (CC * NCH);
    float e = __expf(td[c]);
    float d = __expf(-e);
    size_t idx = ((size_t)b * NCH + j) * CC + c;
    float a = g_Sa[idx], bb = g_Sb[idx];
    size_t base = ((size_t)b * TT + (size_t)j * LCH) * CC + c;
    #pragma unroll 4
    for (int t = 0; t < LCH; t++) {
        size_t p = base + (size_t)t * CC;
        float ek = __expf(g_k[p]);
        a  = d * a  + ek * g_v[p];
        bb = d * bb + ek;
        float wkv = a / (bb + 1e-8f);
        g_xmid[p] = x[p] + g_r[p] * wkv;
    }
}

// ---------------- epilogue / state -------------------------------------------
__global__ __launch_bounds__(256) void final_kernel(float* __restrict__ out)
{
    size_t i = ((size_t)blockIdx.x * 256 + threadIdx.x) * 4;
    float4 xm = *(const float4*)&g_xmid[i];
    float4 cr = *(const float4*)&g_cr[i];
    float4 dv = *(const float4*)&g_dv[i];
    float4 o;
    o.x = xm.x + cr.x * dv.x;
    o.y = xm.y + cr.y * dv.y;
    o.z = xm.z + cr.z * dv.z;
    o.w = xm.w + cr.w * dv.w;
    *(float4*)&out[i] = o;
}

__global__ __launch_bounds__(256) void state_kernel(float* __restrict__ out)
{
    int tid = blockIdx.x * 256 + threadIdx.x;   // BB*CC threads
    int c = tid % CC;
    int b = tid / CC;
    out[tid] = g_xln[((size_t)b * TT + (TT - 2)) * CC + c];
}

// ---------------- host launch -------------------------------------------------
extern "C" void kernel_launch(void* const* d_in, const int* in_sizes, int n_in,
                              void* d_out, int out_size)
{
    const float* x     = (const float*)d_in[0];
    const float* ln1_g = (const float*)d_in[1];
    const float* ln1_b = (const float*)d_in[2];
    const float* td    = (const float*)d_in[3];
    const float* Wk    = (const float*)d_in[4];
    const float* Wv    = (const float*)d_in[5];
    const float* Wr    = (const float*)d_in[6];
    const float* ln2_g = (const float*)d_in[7];
    const float* ln2_b = (const float*)d_in[8];
    const float* Wck   = (const float*)d_in[9];
    const float* Wcv   = (const float*)d_in[10];
    const float* Wcr   = (const float*)d_in[11];
    float* out = (float*)d_out;

    float *p_xln, *p_k, *p_v, *p_r, *p_xmid, *p_x2, *p_H, *p_dv, *p_cr;
    cudaGetSymbolAddress((void**)&p_xln,  g_xln);
    cudaGetSymbolAddress((void**)&p_k,    g_k);
    cudaGetSymbolAddress((void**)&p_v,    g_v);
    cudaGetSymbolAddress((void**)&p_r,    g_r);
    cudaGetSymbolAddress((void**)&p_xmid, g_xmid);
    cudaGetSymbolAddress((void**)&p_x2,   g_x2);
    cudaGetSymbolAddress((void**)&p_H,    g_H);
    cudaGetSymbolAddress((void**)&p_dv,   g_dv);
    cudaGetSymbolAddress((void**)&p_cr,   g_cr);

    // 1. LN1
    ln_kernel<<<BT, 256>>>(x, ln1_g, ln1_b, p_xln);

    // 2. state output (xln row T-2 per batch)
    if ((size_t)out_size >= (size_t)BT * CC + (size_t)BB * CC)
        state_kernel<<<(BB * CC) / 256, 256>>>(out + (size_t)BT * CC);

    // 3. k, v (shifted), r
    dim3 gC(CC / 128, BT / 128);
    gemm_kernel<true,  0><<<gC, 256>>>(p_xln, Wk, p_k, BT, CC, CC);
    gemm_kernel<true,  0><<<gC, 256>>>(p_xln, Wv, p_v, BT, CC, CC);
    gemm_kernel<false, 0><<<gC, 256>>>(p_xln, Wr, p_r, BT, CC, CC);

    // 4. WKV chunked scan + residual
    wkv_passA<<<(BB * NCH * CC) / 256, 256>>>(td);
    wkv_passB<<<(BB * CC) / 256, 256>>>(td);
    wkv_passC<<<(BB * NCH * CC) / 256, 256>>>(td, x);

    // 5. LN2
    ln_kernel<<<BT, 256>>>(p_xmid, ln2_g, ln2_b, p_x2);

    // 6. channel-mix GEMMs
    dim3 gF(FF / 128, BT / 128);
    gemm_kernel<false, 1><<<gF, 256>>>(p_x2, Wck, p_H, BT, FF, CC);   // relu^2
    gemm_kernel<false, 0><<<gC, 256>>>(p_H,  Wcv, p_dv, BT, CC, FF);
    gemm_kernel<false, 2><<<gC, 256>>>(p_x2, Wcr, p_cr, BT, CC, CC);  // sigmoid

    // 7. out = xmid + cr * dv
    final_kernel<<<((size_t)BT * CC / 4) / 256, 256>>>(out);
}

// round 4
// speedup vs baseline: 2.8646x; 2.8646x over previous
#include <cuda_runtime.h>
#include <cuda_bf16.h>
#include <cstdint>

#define BB 4
#define TT 2048
#define CC 2048
#define FFD 8192
#define BT (BB*TT)          // 8192
#define NCH 64
#define LCH 32

// ---------------- scratch (device globals; no allocation allowed) ----------
__device__ float g_xln [(size_t)BT*CC];
__device__ float g_k   [(size_t)BT*CC];
__device__ float g_v   [(size_t)BT*CC];
__device__ float g_r   [(size_t)BT*CC];
__device__ float g_xmid[(size_t)BT*CC];
__device__ float g_cr  [(size_t)BT*CC];
__device__ float g_Aloc[(size_t)BB*CC*NCH];
__device__ float g_Bloc[(size_t)BB*CC*NCH];
__device__ float g_Sa  [(size_t)BB*CC*NCH];
__device__ float g_Sb  [(size_t)BB*CC*NCH];

// bf16 split planes (hi/lo)
__device__ __nv_bfloat16 g_xph[((size_t)BT+1)*CC];   // padded: row0 = 0, row m+1 = xln row m
__device__ __nv_bfloat16 g_xpl[((size_t)BT+1)*CC];
__device__ __nv_bfloat16 g_x2h[(size_t)BT*CC];
__device__ __nv_bfloat16 g_x2l[(size_t)BT*CC];
__device__ __nv_bfloat16 g_Hh [(size_t)BT*FFD];
__device__ __nv_bfloat16 g_Hl [(size_t)BT*FFD];
__device__ __nv_bfloat16 g_Wkh[(size_t)CC*CC],  g_Wkl[(size_t)CC*CC];
__device__ __nv_bfloat16 g_Wvh[(size_t)CC*CC],  g_Wvl[(size_t)CC*CC];
__device__ __nv_bfloat16 g_Wrh[(size_t)CC*CC],  g_Wrl[(size_t)CC*CC];
__device__ __nv_bfloat16 g_Wcrh[(size_t)CC*CC], g_Wcrl[(size_t)CC*CC];
__device__ __nv_bfloat16 g_Wckh[(size_t)FFD*CC], g_Wckl[(size_t)FFD*CC];
__device__ __nv_bfloat16 g_Wcvh[(size_t)CC*FFD], g_Wcvl[(size_t)CC*FFD];

// ======================= PTX helpers (compute_80-safe) ======================
__device__ __forceinline__ uint32_t smem_u32(const void* p) {
    uint32_t a;
    asm("{ .reg .u64 t; cvta.to.shared.u64 t, %1; cvt.u32.u64 %0, t; }" : "=r"(a) : "l"(p));
    return a;
}
__device__ __forceinline__ void cp_async16(uint32_t dst, const void* src) {
    asm volatile("cp.async.cg.shared.global [%0], [%1], 16;" :: "r"(dst), "l"(src) : "memory");
}
__device__ __forceinline__ void cp_commit() {
    asm volatile("cp.async.commit_group;" ::: "memory");
}
template <int N>
__device__ __forceinline__ void cp_wait() {
    asm volatile("cp.async.wait_group %0;" :: "n"(N) : "memory");
}
__device__ __forceinline__ void ldm_x4(uint32_t* r, uint32_t addr) {
    asm volatile("ldmatrix.sync.aligned.m8n8.x4.shared.b16 {%0,%1,%2,%3}, [%4];"
        : "=r"(r[0]), "=r"(r[1]), "=r"(r[2]), "=r"(r[3]) : "r"(addr));
}
__device__ __forceinline__ void ldm_x2(uint32_t* r, uint32_t addr) {
    asm volatile("ldmatrix.sync.aligned.m8n8.x2.shared.b16 {%0,%1}, [%2];"
        : "=r"(r[0]), "=r"(r[1]) : "r"(addr));
}
__device__ __forceinline__ void mma_bf16(float* d, const uint32_t* a, const uint32_t* b) {
    asm volatile(
        "mma.sync.aligned.m16n8k16.row.col.f32.bf16.bf16.f32 "
        "{%0,%1,%2,%3}, {%4,%5,%6,%7}, {%8,%9}, {%0,%1,%2,%3};"
        : "+f"(d[0]), "+f"(d[1]), "+f"(d[2]), "+f"(d[3])
        : "r"(a[0]), "r"(a[1]), "r"(a[2]), "r"(a[3]), "r"(b[0]), "r"(b[1]));
}
__device__ __forceinline__ uint32_t pk(__nv_bfloat16 a, __nv_bfloat16 b) {
    return (uint32_t)__bfloat16_as_ushort(a) | ((uint32_t)__bfloat16_as_ushort(b) << 16);
}

// ======================= HMMA GEMM ==========================================
// Y[M,N] = A[M,K] @ W[N,K]^T via bf16 hi/lo split (3 MMAs per k-step).
// BM=128, BN=128, BK=32, 256 threads, 3-stage cp.async pipeline.
// Stage s of the K-loop lives in buffer s % NSTAGE (fixed from round 3's bug).
// Smem per stage: 4 tiles (Ah, Al, Wh, Wl), each 128 rows x 80B pitch (32 bf16 data).
// EPI: 0 fp32 | 1 relu^2 -> bf16 hi/lo planes | 2 sigmoid fp32 | 3 out = xadd + xmul*acc
#define ROWB 80u
#define TILEB (128u*ROWB)         // 10240
#define STAGEB (4u*TILEB)         // 40960
#define NSTAGE 3
#define SMEM_BYTES (NSTAGE*STAGEB)

template <int EPI>
__global__ __launch_bounds__(256, 1) void hmma_gemm(
    const __nv_bfloat16* __restrict__ Ah, const __nv_bfloat16* __restrict__ Al,
    const __nv_bfloat16* __restrict__ Wh, const __nv_bfloat16* __restrict__ Wl,
    float* __restrict__ out,
    __nv_bfloat16* __restrict__ oh, __nv_bfloat16* __restrict__ ol,
    const float* __restrict__ xadd, const float* __restrict__ xmul,
    int N, int K)
{
    extern __shared__ char smem[];
    const uint32_t sbase = smem_u32(smem);
    const int tid  = threadIdx.x;
    const int lane = tid & 31;
    const int wid  = tid >> 5;
    const int warp_m = wid & 1;         // 2 warps in M
    const int warp_n = wid >> 1;        // 4 warps in N
    const int m0 = blockIdx.y * 128;
    const int n0 = blockIdx.x * 128;
    const int S = K >> 5;               // K / 32

    // --- loader mapping: 2048 chunks of 16B per stage, 8 per thread ---------
    // idx: tile = idx>>9 (0 Ah, 1 Al, 2 Wh, 3 Wl), r = (idx>>2)&127, s = idx&3
    const __nv_bfloat16* srcBase[4] = {
        Ah + (size_t)m0 * K, Al + (size_t)m0 * K,
        Wh + (size_t)n0 * K, Wl + (size_t)n0 * K };

    auto load_stage = [&](int buf, int i) {
        const int k0 = i << 5;
        const uint32_t stage = sbase + buf * STAGEB;
        #pragma unroll
        for (int rep = 0; rep < 8; rep++) {
            const int idx = tid + rep * 256;
            const int tile = idx >> 9;
            const int r = (idx >> 2) & 127;
            const int s = idx & 3;
            const __nv_bfloat16* src = srcBase[tile] + (size_t)r * K + k0 + s * 8;
            cp_async16(stage + tile * TILEB + r * ROWB + s * 16, src);
        }
    };

    // prologue: stage s -> buffer s % NSTAGE
    load_stage(0, 0); cp_commit();
    load_stage(1, 1); cp_commit();

    float acc[4][4][4];
    #pragma unroll
    for (int mt = 0; mt < 4; mt++)
        #pragma unroll
        for (int nt = 0; nt < 4; nt++)
            #pragma unroll
            for (int q = 0; q < 4; q++) acc[mt][nt][q] = 0.f;

    // ldmatrix per-lane offsets (bytes)
    const uint32_t aoff = (lane & 15) * ROWB + (lane >> 4) * 16;
    const uint32_t boff = (lane & 7) * ROWB + ((lane >> 3) & 1) * 16;

    cp_wait<1>();          // stage 0 resident
    __syncthreads();

    for (int i = 0; i < S; i++) {
        const uint32_t sb = sbase + (i % NSTAGE) * STAGEB;
        #pragma unroll
        for (int ks = 0; ks < 2; ks++) {
            const uint32_t kb = ks * 32;   // 16 cols * 2B
            uint32_t ahf[4][4], alf[4][4];
            #pragma unroll
            for (int mt = 0; mt < 4; mt++) {
                const uint32_t base = sb + (warp_m * 64 + mt * 16) * ROWB + kb + aoff;
                ldm_x4(ahf[mt], base);
                ldm_x4(alf[mt], base + TILEB);
            }
            uint32_t bhf[4][2], blf[4][2];
            #pragma unroll
            for (int nt = 0; nt < 4; nt++) {
                const uint32_t base = sb + 2 * TILEB + (warp_n * 32 + nt * 8) * ROWB + kb + boff;
                ldm_x2(bhf[nt], base);
                ldm_x2(blf[nt], base + TILEB);
            }
            #pragma unroll
            for (int mt = 0; mt < 4; mt++)
                #pragma unroll
                for (int nt = 0; nt < 4; nt++) {
                    mma_bf16(acc[mt][nt], ahf[mt], bhf[nt]);
                    mma_bf16(acc[mt][nt], alf[mt], bhf[nt]);
                    mma_bf16(acc[mt][nt], ahf[mt], blf[nt]);
                }
        }
        // refill buffer (i+2) % NSTAGE == (i-1) % NSTAGE, consumed at i-1 and
        // published by the barrier at the end of iteration i-1.
        if (i + 2 < S) load_stage((i + 2) % NSTAGE, i + 2);
        cp_commit();
        cp_wait<1>();      // stage i+1 resident
        __syncthreads();
    }

    // ---------------- epilogue --------------------------------------------
    const int rbase = m0 + warp_m * 64 + (lane >> 2);
    const int cbase = n0 + warp_n * 32 + (lane & 3) * 2;
    #pragma unroll
    for (int mt = 0; mt < 4; mt++) {
        #pragma unroll
        for (int nt = 0; nt < 4; nt++) {
            const float* c = acc[mt][nt];
            const size_t r0 = (size_t)(rbase + mt * 16);
            const size_t r1 = r0 + 8;
            const int col = cbase + nt * 8;
            if (EPI == 0) {
                *(float2*)&out[r0 * N + col] = make_float2(c[0], c[1]);
                *(float2*)&out[r1 * N + col] = make_float2(c[2], c[3]);
            } else if (EPI == 2) {
                *(float2*)&out[r0 * N + col] = make_float2(
                    1.f / (1.f + __expf(-c[0])), 1.f / (1.f + __expf(-c[1])));
                *(float2*)&out[r1 * N + col] = make_float2(
                    1.f / (1.f + __expf(-c[2])), 1.f / (1.f + __expf(-c[3])));
            } else if (EPI == 3) {
                float2 a0 = *(const float2*)&xadd[r0 * N + col];
                float2 m0v = *(const float2*)&xmul[r0 * N + col];
                float2 a1 = *(const float2*)&xadd[r1 * N + col];
                float2 m1v = *(const float2*)&xmul[r1 * N + col];
                *(float2*)&out[r0 * N + col] = make_float2(
                    a0.x + m0v.x * c[0], a0.y + m0v.y * c[1]);
                *(float2*)&out[r1 * N + col] = make_float2(
                    a1.x + m1v.x * c[2], a1.y + m1v.y * c[3]);
            } else {  // EPI == 1: relu^2 -> bf16 hi/lo split planes
                float f0 = c[0] > 0.f ? c[0] * c[0] : 0.f;
                float f1 = c[1] > 0.f ? c[1] * c[1] : 0.f;
                float f2 = c[2] > 0.f ? c[2] * c[2] : 0.f;
                float f3 = c[3] > 0.f ? c[3] * c[3] : 0.f;
                __nv_bfloat16 h0 = __float2bfloat16(f0), h1 = __float2bfloat16(f1);
                __nv_bfloat16 h2 = __float2bfloat16(f2), h3 = __float2bfloat16(f3);
                *(uint32_t*)&oh[r0 * N + col] = pk(h0, h1);
                *(uint32_t*)&oh[r1 * N + col] = pk(h2, h3);
                *(uint32_t*)&ol[r0 * N + col] = pk(
                    __float2bfloat16(f0 - __bfloat162float(h0)),
                    __float2bfloat16(f1 - __bfloat162float(h1)));
                *(uint32_t*)&ol[r1 * N + col] = pk(
                    __float2bfloat16(f2 - __bfloat162float(h2)),
                    __float2bfloat16(f3 - __bfloat162float(h3)));
            }
        }
    }
}

// ======================= layernorm (+ bf16 split planes) ====================
__device__ __forceinline__ void blockReduce2(float& a, float& b) {
    __shared__ float sa[8], sb[8];
    int lane = threadIdx.x & 31, w = threadIdx.x >> 5;
    #pragma unroll
    for (int o = 16; o > 0; o >>= 1) {
        a += __shfl_down_sync(0xffffffffu, a, o);
        b += __shfl_down_sync(0xffffffffu, b, o);
    }
    if (lane == 0) { sa[w] = a; sb[w] = b; }
    __syncthreads();
    if (w == 0) {
        a = (lane < 8) ? sa[lane] : 0.f;
        b = (lane < 8) ? sb[lane] : 0.f;
        #pragma unroll
        for (int o = 4; o > 0; o >>= 1) {
            a += __shfl_down_sync(0xffffffffu, a, o);
            b += __shfl_down_sync(0xffffffffu, b, o);
        }
        if (lane == 0) { sa[0] = a; sb[0] = b; }
    }
    __syncthreads();
    a = sa[0]; b = sb[0];
    __syncthreads();
}

__global__ __launch_bounds__(256) void ln_kernel(
    const float* __restrict__ x, const float* __restrict__ g,
    const float* __restrict__ bia, float* __restrict__ y,
    __nv_bfloat16* __restrict__ yh, __nv_bfloat16* __restrict__ yl)
{
    size_t row = blockIdx.x;
    const float* xr = x + row * CC;
    float s = 0.f, q = 0.f;
    for (int i = threadIdx.x; i < CC; i += 256) {
        float v = xr[i];
        s += v; q += v * v;
    }
    blockReduce2(s, q);
    float mu = s * (1.f / CC);
    float var = q * (1.f / CC) - mu * mu;
    float rstd = rsqrtf(var + 1e-5f);
    for (int i = threadIdx.x; i < CC; i += 256) {
        float v = (xr[i] - mu) * rstd * g[i] + bia[i];
        y[row * CC + i] = v;
        __nv_bfloat16 h = __float2bfloat16(v);
        yh[row * CC + i] = h;
        yl[row * CC + i] = __float2bfloat16(v - __bfloat162float(h));
    }
}

// ======================= converters / misc ==================================
__global__ __launch_bounds__(256) void conv_split(
    const float4* __restrict__ src, uint2* __restrict__ hi, uint2* __restrict__ lo)
{
    size_t i = (size_t)blockIdx.x * 256 + threadIdx.x;
    float4 f = src[i];
    __nv_bfloat16 h0 = __float2bfloat16(f.x), h1 = __float2bfloat16(f.y);
    __nv_bfloat16 h2 = __float2bfloat16(f.z), h3 = __float2bfloat16(f.w);
    hi[i] = make_uint2(pk(h0, h1), pk(h2, h3));
    lo[i] = make_uint2(
        pk(__float2bfloat16(f.x - __bfloat162float(h0)), __float2bfloat16(f.y - __bfloat162float(h1))),
        pk(__float2bfloat16(f.z - __bfloat162float(h2)), __float2bfloat16(f.w - __bfloat162float(h3))));
}

__global__ __launch_bounds__(256) void zero2(__nv_bfloat16* a, __nv_bfloat16* b)
{
    int i = blockIdx.x * 256 + threadIdx.x;
    a[i] = __float2bfloat16(0.f);
    b[i] = __float2bfloat16(0.f);
}

// ======================= WKV chunked scan ===================================
__global__ __launch_bounds__(256) void wkv_passA(const float* __restrict__ td)
{
    int tid = blockIdx.x * 256 + threadIdx.x;
    int c = tid % CC;
    int j = (tid / CC) % NCH;
    int b = tid / (CC * NCH);
    float d = __expf(-__expf(td[c]));
    float a = 0.f, bb = 0.f;
    size_t base = ((size_t)b * TT + (size_t)j * LCH) * CC + c;
    for (int t = 0; t < LCH; t++) {
        float ek = __expf(g_k[base + (size_t)t * CC]);
        float vv = g_v[base + (size_t)t * CC];
        if (j == 0 && t == 0) { ek = 1.f; vv = 0.f; }   // t_global==0: shifted row is 0
        a  = d * a  + ek * vv;
        bb = d * bb + ek;
    }
    size_t idx = ((size_t)b * NCH + j) * CC + c;
    g_Aloc[idx] = a;
    g_Bloc[idx] = bb;
}

__global__ __launch_bounds__(256) void wkv_passB(const float* __restrict__ td)
{
    int tid = blockIdx.x * 256 + threadIdx.x;
    int c = tid % CC;
    int b = tid / CC;
    float dL = __expf(-(float)LCH * __expf(td[c]));
    float sa = 0.f, sb = 0.f;
    for (int j = 0; j < NCH; j++) {
        size_t idx = ((size_t)b * NCH + j) * CC + c;
        g_Sa[idx] = sa;
        g_Sb[idx] = sb;
        sa = dL * sa + g_Aloc[idx];
        sb = dL * sb + g_Bloc[idx];
    }
}

__global__ __launch_bounds__(256) void wkv_passC(
    const float* __restrict__ td, const float* __restrict__ x)
{
    int tid = blockIdx.x * 256 + threadIdx.x;
    int c = tid % CC;
    int j = (tid / CC) % NCH;
    int b = tid / (CC * NCH);
    float d = __expf(-__expf(td[c]));
    size_t idx = ((size_t)b * NCH + j) * CC + c;
    float a = g_Sa[idx], bb = g_Sb[idx];
    size_t base = ((size_t)b * TT + (size_t)j * LCH) * CC + c;
    for (int t = 0; t < LCH; t++) {
        size_t p = base + (size_t)t * CC;
        float ek = __expf(g_k[p]);
        float vv = g_v[p];
        if (j == 0 && t == 0) { ek = 1.f; vv = 0.f; }
        a  = d * a  + ek * vv;
        bb = d * bb + ek;
        g_xmid[p] = x[p] + g_r[p] * (a / (bb + 1e-8f));
    }
}

__global__ __launch_bounds__(256) void state_kernel(float* __restrict__ out)
{
    int tid = blockIdx.x * 256 + threadIdx.x;
    int c = tid % CC;
    int b = tid / CC;
    out[tid] = g_xln[((size_t)b * TT + (TT - 2)) * CC + c];
}

// ======================= host launch =========================================
extern "C" void kernel_launch(void* const* d_in, const int* in_sizes, int n_in,
                              void* d_out, int out_size)
{
    const float* x     = (const float*)d_in[0];
    const float* ln1_g = (const float*)d_in[1];
    const float* ln1_b = (const float*)d_in[2];
    const float* td    = (const float*)d_in[3];
    const float* Wk    = (const float*)d_in[4];
    const float* Wv    = (const float*)d_in[5];
    const float* Wr    = (const float*)d_in[6];
    const float* ln2_g = (const float*)d_in[7];
    const float* ln2_b = (const float*)d_in[8];
    const float* Wck   = (const float*)d_in[9];
    const float* Wcv   = (const float*)d_in[10];
    const float* Wcr   = (const float*)d_in[11];
    float* out = (float*)d_out;

    float *p_xln, *p_k, *p_v, *p_r, *p_xmid, *p_cr;
    __nv_bfloat16 *p_xph, *p_xpl, *p_x2h, *p_x2l, *p_Hh, *p_Hl;
    __nv_bfloat16 *p_Wkh, *p_Wkl, *p_Wvh, *p_Wvl, *p_Wrh, *p_Wrl;
    __nv_bfloat16 *p_Wcrh, *p_Wcrl, *p_Wckh, *p_Wckl, *p_Wcvh, *p_Wcvl;
    cudaGetSymbolAddress((void**)&p_xln,  g_xln);
    cudaGetSymbolAddress((void**)&p_k,    g_k);
    cudaGetSymbolAddress((void**)&p_v,    g_v);
    cudaGetSymbolAddress((void**)&p_r,    g_r);
    cudaGetSymbolAddress((void**)&p_xmid, g_xmid);
    cudaGetSymbolAddress((void**)&p_cr,   g_cr);
    cudaGetSymbolAddress((void**)&p_xph,  g_xph);
    cudaGetSymbolAddress((void**)&p_xpl,  g_xpl);
    cudaGetSymbolAddress((void**)&p_x2h,  g_x2h);
    cudaGetSymbolAddress((void**)&p_x2l,  g_x2l);
    cudaGetSymbolAddress((void**)&p_Hh,   g_Hh);
    cudaGetSymbolAddress((void**)&p_Hl,   g_Hl);
    cudaGetSymbolAddress((void**)&p_Wkh,  g_Wkh);  cudaGetSymbolAddress((void**)&p_Wkl,  g_Wkl);
    cudaGetSymbolAddress((void**)&p_Wvh,  g_Wvh);  cudaGetSymbolAddress((void**)&p_Wvl,  g_Wvl);
    cudaGetSymbolAddress((void**)&p_Wrh,  g_Wrh);  cudaGetSymbolAddress((void**)&p_Wrl,  g_Wrl);
    cudaGetSymbolAddress((void**)&p_Wcrh, g_Wcrh); cudaGetSymbolAddress((void**)&p_Wcrl, g_Wcrl);
    cudaGetSymbolAddress((void**)&p_Wckh, g_Wckh); cudaGetSymbolAddress((void**)&p_Wckl, g_Wckl);
    cudaGetSymbolAddress((void**)&p_Wcvh, g_Wcvh); cudaGetSymbolAddress((void**)&p_Wcvl, g_Wcvl);

    cudaFuncSetAttribute(hmma_gemm<0>, cudaFuncAttributeMaxDynamicSharedMemorySize, SMEM_BYTES);
    cudaFuncSetAttribute(hmma_gemm<1>, cudaFuncAttributeMaxDynamicSharedMemorySize, SMEM_BYTES);
    cudaFuncSetAttribute(hmma_gemm<2>, cudaFuncAttributeMaxDynamicSharedMemorySize, SMEM_BYTES);
    cudaFuncSetAttribute(hmma_gemm<3>, cudaFuncAttributeMaxDynamicSharedMemorySize, SMEM_BYTES);

    // weight splits (weights are inputs; convert every launch)
    conv_split<<<(CC*CC)/1024,  256>>>((const float4*)Wk,  (uint2*)p_Wkh,  (uint2*)p_Wkl);
    conv_split<<<(CC*CC)/1024,  256>>>((const float4*)Wv,  (uint2*)p_Wvh,  (uint2*)p_Wvl);
    conv_split<<<(CC*CC)/1024,  256>>>((const float4*)Wr,  (uint2*)p_Wrh,  (uint2*)p_Wrl);
    conv_split<<<(CC*CC)/1024,  256>>>((const float4*)Wcr, (uint2*)p_Wcrh, (uint2*)p_Wcrl);
    conv_split<<<(FFD*CC)/1024, 256>>>((const float4*)Wck, (uint2*)p_Wckh, (uint2*)p_Wckl);
    conv_split<<<(CC*FFD)/1024, 256>>>((const float4*)Wcv, (uint2*)p_Wcvh, (uint2*)p_Wcvl);

    // LN1 -> xln fp32 + padded bf16 planes (row m stored at plane row m+1)
    ln_kernel<<<BT, 256>>>(x, ln1_g, ln1_b, p_xln, p_xph + CC, p_xpl + CC);
    zero2<<<CC/256, 256>>>(p_xph, p_xpl);

    if ((size_t)out_size >= (size_t)BT * CC + (size_t)BB * CC)
        state_kernel<<<(BB * CC) / 256, 256>>>(out + (size_t)BT * CC);

    // k, v (shifted planes base), r (unshifted = +CC)
    dim3 gC(CC / 128, BT / 128);
    hmma_gemm<0><<<gC, 256, SMEM_BYTES>>>(p_xph,      p_xpl,      p_Wkh, p_Wkl, p_k, 0,0,0,0, CC, CC);
    hmma_gemm<0><<<gC, 256, SMEM_BYTES>>>(p_xph,      p_xpl,      p_Wvh, p_Wvl, p_v, 0,0,0,0, CC, CC);
    hmma_gemm<0><<<gC, 256, SMEM_BYTES>>>(p_xph + CC, p_xpl + CC, p_Wrh, p_Wrl, p_r, 0,0,0,0, CC, CC);

    // WKV scan + residual -> xmid
    wkv_passA<<<(BB * NCH * CC) / 256, 256>>>(td);
    wkv_passB<<<(BB * CC) / 256, 256>>>(td);
    wkv_passC<<<(BB * NCH * CC) / 256, 256>>>(td, x);

    // LN2 -> x2 planes (fp32 dump reuses g_xln; state already copied)
    ln_kernel<<<BT, 256>>>(p_xmid, ln2_g, ln2_b, p_xln, p_x2h, p_x2l);

    // channel mix
    dim3 gF(FFD / 128, BT / 128);
    hmma_gemm<1><<<gF, 256, SMEM_BYTES>>>(p_x2h, p_x2l, p_Wckh, p_Wckl, 0, p_Hh, p_Hl, 0,0, FFD, CC);    // relu^2 -> H planes
    hmma_gemm<2><<<gC, 256, SMEM_BYTES>>>(p_x2h, p_x2l, p_Wcrh, p_Wcrl, p_cr, 0,0,0,0, CC, CC);          // sigmoid -> cr
    hmma_gemm<3><<<gC, 256, SMEM_BYTES>>>(p_Hh,  p_Hl,  p_Wcvh, p_Wcvl, out, 0,0, p_xmid, p_cr, CC, FFD); // out = xmid + cr*dv
}

// round 5
// speedup vs baseline: 3.9720x; 1.3866x over previous
#include <cuda_runtime.h>
#include <cuda_fp16.h>
#include <cstdint>

#define BB 4
#define TT 2048
#define CC 2048
#define FFD 8192
#define BT (BB*TT)          // 8192
#define NCH 64
#define LCH 32

// ---------------- scratch (device globals; no allocation allowed) ----------
__device__ float g_xln [(size_t)BT*CC];
__device__ float g_k   [(size_t)BT*CC];
__device__ float g_v   [(size_t)BT*CC];
__device__ float g_r   [(size_t)BT*CC];
__device__ float g_xmid[(size_t)BT*CC];
__device__ float g_cr  [(size_t)BT*CC];
__device__ float g_Aloc[(size_t)BB*CC*NCH];
__device__ float g_Bloc[(size_t)BB*CC*NCH];
__device__ float g_Sa  [(size_t)BB*CC*NCH];
__device__ float g_Sb  [(size_t)BB*CC*NCH];

// fp16 split planes: activations hi/lo (exact to 2^-22), weights hi only
__device__ __half g_xph[((size_t)BT+1)*CC];   // padded: row0 = 0, row m+1 = xln row m
__device__ __half g_xpl[((size_t)BT+1)*CC];
__device__ __half g_x2h[(size_t)BT*CC];
__device__ __half g_x2l[(size_t)BT*CC];
__device__ __half g_Hh [(size_t)BT*FFD];
__device__ __half g_Hl [(size_t)BT*FFD];
__device__ __half g_Wkh [(size_t)CC*CC];
__device__ __half g_Wvh [(size_t)CC*CC];
__device__ __half g_Wrh [(size_t)CC*CC];
__device__ __half g_Wcrh[(size_t)CC*CC];
__device__ __half g_Wckh[(size_t)FFD*CC];
__device__ __half g_Wcvh[(size_t)CC*FFD];

// ======================= PTX helpers (compute_80-safe) ======================
__device__ __forceinline__ uint32_t smem_u32(const void* p) {
    uint32_t a;
    asm("{ .reg .u64 t; cvta.to.shared.u64 t, %1; cvt.u32.u64 %0, t; }" : "=r"(a) : "l"(p));
    return a;
}
__device__ __forceinline__ void cp_async16(uint32_t dst, const void* src) {
    asm volatile("cp.async.cg.shared.global [%0], [%1], 16;" :: "r"(dst), "l"(src) : "memory");
}
__device__ __forceinline__ void cp_commit() {
    asm volatile("cp.async.commit_group;" ::: "memory");
}
template <int N>
__device__ __forceinline__ void cp_wait() {
    asm volatile("cp.async.wait_group %0;" :: "n"(N) : "memory");
}
__device__ __forceinline__ void ldm_x4(uint32_t* r, uint32_t addr) {
    asm volatile("ldmatrix.sync.aligned.m8n8.x4.shared.b16 {%0,%1,%2,%3}, [%4];"
        : "=r"(r[0]), "=r"(r[1]), "=r"(r[2]), "=r"(r[3]) : "r"(addr));
}
__device__ __forceinline__ void ldm_x2(uint32_t* r, uint32_t addr) {
    asm volatile("ldmatrix.sync.aligned.m8n8.x2.shared.b16 {%0,%1}, [%2];"
        : "=r"(r[0]), "=r"(r[1]) : "r"(addr));
}
__device__ __forceinline__ void mma_f16(float* d, const uint32_t* a, const uint32_t* b) {
    asm volatile(
        "mma.sync.aligned.m16n8k16.row.col.f32.f16.f16.f32 "
        "{%0,%1,%2,%3}, {%4,%5,%6,%7}, {%8,%9}, {%0,%1,%2,%3};"
        : "+f"(d[0]), "+f"(d[1]), "+f"(d[2]), "+f"(d[3])
        : "r"(a[0]), "r"(a[1]), "r"(a[2]), "r"(a[3]), "r"(b[0]), "r"(b[1]));
}
__device__ __forceinline__ uint32_t pkh(__half a, __half b) {
    return (uint32_t)__half_as_ushort(a) | ((uint32_t)__half_as_ushort(b) << 16);
}

// ======================= HMMA GEMM ==========================================
// Y[M,N] = A[M,K] @ W[N,K]^T, A exact in fp16 hi+lo, W quantized fp16 hi.
// 2 MMAs per k-step: Ah*Wh + Al*Wh. BM=128, BN=128, BK=32, 256 threads,
// 4-stage cp.async pipeline; stage s lives in buffer s % NSTAGE.
// Smem per stage: 3 tiles (Ah, Al, Wh), each 128 rows x 80B pitch (32 fp16 data).
// EPI: 0 fp32 | 1 relu^2 -> fp16 hi/lo planes | 2 sigmoid fp32 | 3 out = xadd + xmul*acc
#define ROWB 80u
#define TILEB (128u*ROWB)         // 10240
#define STAGEB (3u*TILEB)         // 30720
#define NSTAGE 4
#define SMEM_BYTES (NSTAGE*STAGEB)

template <int EPI>
__global__ __launch_bounds__(256, 1) void hmma_gemm(
    const __half* __restrict__ Ah, const __half* __restrict__ Al,
    const __half* __restrict__ Wh,
    float* __restrict__ out,
    __half* __restrict__ oh, __half* __restrict__ ol,
    const float* __restrict__ xadd, const float* __restrict__ xmul,
    int N, int K)
{
    extern __shared__ char smem[];
    const uint32_t sbase = smem_u32(smem);
    const int tid  = threadIdx.x;
    const int lane = tid & 31;
    const int wid  = tid >> 5;
    const int warp_m = wid & 1;         // 2 warps in M
    const int warp_n = wid >> 1;        // 4 warps in N
    const int m0 = blockIdx.y * 128;
    const int n0 = blockIdx.x * 128;
    const int S = K >> 5;               // K / 32  (>= 64 here)

    // --- loader mapping: 1536 chunks of 16B per stage, 6 per thread ---------
    // idx: tile = idx>>9 (0 Ah, 1 Al, 2 Wh), r = (idx>>2)&127, s = idx&3
    const __half* srcBase[3] = {
        Ah + (size_t)m0 * K, Al + (size_t)m0 * K, Wh + (size_t)n0 * K };

    auto load_stage = [&](int buf, int i) {
        const int k0 = i << 5;
        const uint32_t stage = sbase + buf * STAGEB;
        #pragma unroll
        for (int rep = 0; rep < 6; rep++) {
            const int idx = tid + rep * 256;
            const int tile = idx >> 9;
            const int r = (idx >> 2) & 127;
            const int s = idx & 3;
            const __half* src = srcBase[tile] + (size_t)r * K + k0 + s * 8;
            cp_async16(stage + tile * TILEB + r * ROWB + s * 16, src);
        }
    };

    // prologue: stages 0..NSTAGE-2
    load_stage(0, 0); cp_commit();
    load_stage(1, 1); cp_commit();
    load_stage(2, 2); cp_commit();

    float acc[4][4][4];
    #pragma unroll
    for (int mt = 0; mt < 4; mt++)
        #pragma unroll
        for (int nt = 0; nt < 4; nt++)
            #pragma unroll
            for (int q = 0; q < 4; q++) acc[mt][nt][q] = 0.f;

    // ldmatrix per-lane offsets (bytes)
    const uint32_t aoff = (lane & 15) * ROWB + (lane >> 4) * 16;
    const uint32_t boff = (lane & 7) * ROWB + ((lane >> 3) & 1) * 16;

    for (int i = 0; i < S; i++) {
        cp_wait<NSTAGE - 2>();      // stage i resident (groups 0..i complete)
        __syncthreads();
        const uint32_t sb = sbase + (i % NSTAGE) * STAGEB;
        #pragma unroll
        for (int ks = 0; ks < 2; ks++) {
            const uint32_t kb = ks * 32;   // 16 cols * 2B
            uint32_t ahf[4][4], alf[4][4];
            #pragma unroll
            for (int mt = 0; mt < 4; mt++) {
                const uint32_t base = sb + (warp_m * 64 + mt * 16) * ROWB + kb + aoff;
                ldm_x4(ahf[mt], base);
                ldm_x4(alf[mt], base + TILEB);
            }
            uint32_t bhf[4][2];
            #pragma unroll
            for (int nt = 0; nt < 4; nt++) {
                const uint32_t base = sb + 2 * TILEB + (warp_n * 32 + nt * 8) * ROWB + kb + boff;
                ldm_x2(bhf[nt], base);
            }
            #pragma unroll
            for (int mt = 0; mt < 4; mt++)
                #pragma unroll
                for (int nt = 0; nt < 4; nt++) {
                    mma_f16(acc[mt][nt], ahf[mt], bhf[nt]);
                    mma_f16(acc[mt][nt], alf[mt], bhf[nt]);
                }
        }
        // refill buffer (i+3)%NSTAGE == (i-1)%NSTAGE (consumed at iter i-1,
        // all warps past it via this iteration's entry barrier).
        if (i + 3 < S) load_stage((i + 3) % NSTAGE, i + 3);
        cp_commit();
    }

    // ---------------- epilogue --------------------------------------------
    const int rbase = m0 + warp_m * 64 + (lane >> 2);
    const int cbase = n0 + warp_n * 32 + (lane & 3) * 2;
    #pragma unroll
    for (int mt = 0; mt < 4; mt++) {
        #pragma unroll
        for (int nt = 0; nt < 4; nt++) {
            const float* c = acc[mt][nt];
            const size_t r0 = (size_t)(rbase + mt * 16);
            const size_t r1 = r0 + 8;
            const int col = cbase + nt * 8;
            if (EPI == 0) {
                *(float2*)&out[r0 * N + col] = make_float2(c[0], c[1]);
                *(float2*)&out[r1 * N + col] = make_float2(c[2], c[3]);
            } else if (EPI == 2) {
                *(float2*)&out[r0 * N + col] = make_float2(
                    1.f / (1.f + __expf(-c[0])), 1.f / (1.f + __expf(-c[1])));
                *(float2*)&out[r1 * N + col] = make_float2(
                    1.f / (1.f + __expf(-c[2])), 1.f / (1.f + __expf(-c[3])));
            } else if (EPI == 3) {
                float2 a0 = *(const float2*)&xadd[r0 * N + col];
                float2 m0v = *(const float2*)&xmul[r0 * N + col];
                float2 a1 = *(const float2*)&xadd[r1 * N + col];
                float2 m1v = *(const float2*)&xmul[r1 * N + col];
                *(float2*)&out[r0 * N + col] = make_float2(
                    a0.x + m0v.x * c[0], a0.y + m0v.y * c[1]);
                *(float2*)&out[r1 * N + col] = make_float2(
                    a1.x + m1v.x * c[2], a1.y + m1v.y * c[3]);
            } else {  // EPI == 1: relu^2 -> fp16 hi/lo split planes
                float f0 = c[0] > 0.f ? c[0] * c[0] : 0.f;
                float f1 = c[1] > 0.f ? c[1] * c[1] : 0.f;
                float f2 = c[2] > 0.f ? c[2] * c[2] : 0.f;
                float f3 = c[3] > 0.f ? c[3] * c[3] : 0.f;
                __half h0 = __float2half_rn(f0), h1 = __float2half_rn(f1);
                __half h2 = __float2half_rn(f2), h3 = __float2half_rn(f3);
                *(uint32_t*)&oh[r0 * N + col] = pkh(h0, h1);
                *(uint32_t*)&oh[r1 * N + col] = pkh(h2, h3);
                *(uint32_t*)&ol[r0 * N + col] = pkh(
                    __float2half_rn(f0 - __half2float(h0)),
                    __float2half_rn(f1 - __half2float(h1)));
                *(uint32_t*)&ol[r1 * N + col] = pkh(
                    __float2half_rn(f2 - __half2float(h2)),
                    __float2half_rn(f3 - __half2float(h3)));
            }
        }
    }
}

// ======================= layernorm (+ fp16 split planes) ====================
__device__ __forceinline__ void blockReduce2(float& a, float& b) {
    __shared__ float sa[8], sb[8];
    int lane = threadIdx.x & 31, w = threadIdx.x >> 5;
    #pragma unroll
    for (int o = 16; o > 0; o >>= 1) {
        a += __shfl_down_sync(0xffffffffu, a, o);
        b += __shfl_down_sync(0xffffffffu, b, o);
    }
    if (lane == 0) { sa[w] = a; sb[w] = b; }
    __syncthreads();
    if (w == 0) {
        a = (lane < 8) ? sa[lane] : 0.f;
        b = (lane < 8) ? sb[lane] : 0.f;
        #pragma unroll
        for (int o = 4; o > 0; o >>= 1) {
            a += __shfl_down_sync(0xffffffffu, a, o);
            b += __shfl_down_sync(0xffffffffu, b, o);
        }
        if (lane == 0) { sa[0] = a; sb[0] = b; }
    }
    __syncthreads();
    a = sa[0]; b = sb[0];
    __syncthreads();
}

__global__ __launch_bounds__(256) void ln_kernel(
    const float* __restrict__ x, const float* __restrict__ g,
    const float* __restrict__ bia, float* __restrict__ y,
    __half* __restrict__ yh, __half* __restrict__ yl)
{
    size_t row = blockIdx.x;
    const float* xr = x + row * CC;
    float s = 0.f, q = 0.f;
    for (int i = threadIdx.x; i < CC; i += 256) {
        float v = xr[i];
        s += v; q += v * v;
    }
    blockReduce2(s, q);
    float mu = s * (1.f / CC);
    float var = q * (1.f / CC) - mu * mu;
    float rstd = rsqrtf(var + 1e-5f);
    for (int i = threadIdx.x; i < CC; i += 256) {
        float v = (xr[i] - mu) * rstd * g[i] + bia[i];
        y[row * CC + i] = v;
        __half h = __float2half_rn(v);
        yh[row * CC + i] = h;
        yl[row * CC + i] = __float2half_rn(v - __half2float(h));
    }
}

// ======================= converters / misc ==================================
__global__ __launch_bounds__(256) void conv_h(
    const float4* __restrict__ src, uint2* __restrict__ hi)
{
    size_t i = (size_t)blockIdx.x * 256 + threadIdx.x;
    float4 f = src[i];
    hi[i] = make_uint2(pkh(__float2half_rn(f.x), __float2half_rn(f.y)),
                       pkh(__float2half_rn(f.z), __float2half_rn(f.w)));
}

__global__ __launch_bounds__(256) void zero2(__half* a, __half* b)
{
    int i = blockIdx.x * 256 + threadIdx.x;
    a[i] = __float2half_rn(0.f);
    b[i] = __float2half_rn(0.f);
}

// ======================= WKV chunked scan ===================================
__global__ __launch_bounds__(256) void wkv_passA(const float* __restrict__ td)
{
    int tid = blockIdx.x * 256 + threadIdx.x;
    int c = tid % CC;
    int j = (tid / CC) % NCH;
    int b = tid / (CC * NCH);
    float d = __expf(-__expf(td[c]));
    float a = 0.f, bb = 0.f;
    size_t base = ((size_t)b * TT + (size_t)j * LCH) * CC + c;
    for (int t = 0; t < LCH; t++) {
        float ek = __expf(g_k[base + (size_t)t * CC]);
        float vv = g_v[base + (size_t)t * CC];
        if (j == 0 && t == 0) { ek = 1.f; vv = 0.f; }   // t_global==0: shifted row is 0
        a  = d * a  + ek * vv;
        bb = d * bb + ek;
    }
    size_t idx = ((size_t)b * NCH + j) * CC + c;
    g_Aloc[idx] = a;
    g_Bloc[idx] = bb;
}

__global__ __launch_bounds__(256) void wkv_passB(const float* __restrict__ td)
{
    int tid = blockIdx.x * 256 + threadIdx.x;
    int c = tid % CC;
    int b = tid / CC;
    float dL = __expf(-(float)LCH * __expf(td[c]));
    float sa = 0.f, sb = 0.f;
    for (int j = 0; j < NCH; j++) {
        size_t idx = ((size_t)b * NCH + j) * CC + c;
        g_Sa[idx] = sa;
        g_Sb[idx] = sb;
        sa = dL * sa + g_Aloc[idx];
        sb = dL * sb + g_Bloc[idx];
    }
}

__global__ __launch_bounds__(256) void wkv_passC(
    const float* __restrict__ td, const float* __restrict__ x)
{
    int tid = blockIdx.x * 256 + threadIdx.x;
    int c = tid % CC;
    int j = (tid / CC) % NCH;
    int b = tid / (CC * NCH);
    float d = __expf(-__expf(td[c]));
    size_t idx = ((size_t)b * NCH + j) * CC + c;
    float a = g_Sa[idx], bb = g_Sb[idx];
    size_t base = ((size_t)b * TT + (size_t)j * LCH) * CC + c;
    for (int t = 0; t < LCH; t++) {
        size_t p = base + (size_t)t * CC;
        float ek = __expf(g_k[p]);
        float vv = g_v[p];
        if (j == 0 && t == 0) { ek = 1.f; vv = 0.f; }
        a  = d * a  + ek * vv;
        bb = d * bb + ek;
        g_xmid[p] = x[p] + g_r[p] * (a / (bb + 1e-8f));
    }
}

__global__ __launch_bounds__(256) void state_kernel(float* __restrict__ out)
{
    int tid = blockIdx.x * 256 + threadIdx.x;
    int c = tid % CC;
    int b = tid / CC;
    out[tid] = g_xln[((size_t)b * TT + (TT - 2)) * CC + c];
}

// ======================= host launch =========================================
extern "C" void kernel_launch(void* const* d_in, const int* in_sizes, int n_in,
                              void* d_out, int out_size)
{
    const float* x     = (const float*)d_in[0];
    const float* ln1_g = (const float*)d_in[1];
    const float* ln1_b = (const float*)d_in[2];
    const float* td    = (const float*)d_in[3];
    const float* Wk    = (const float*)d_in[4];
    const float* Wv    = (const float*)d_in[5];
    const float* Wr    = (const float*)d_in[6];
    const float* ln2_g = (const float*)d_in[7];
    const float* ln2_b = (const float*)d_in[8];
    const float* Wck   = (const float*)d_in[9];
    const float* Wcv   = (const float*)d_in[10];
    const float* Wcr   = (const float*)d_in[11];
    float* out = (float*)d_out;

    float *p_xln, *p_k, *p_v, *p_r, *p_xmid, *p_cr;
    __half *p_xph, *p_xpl, *p_x2h, *p_x2l, *p_Hh, *p_Hl;
    __half *p_Wkh, *p_Wvh, *p_Wrh, *p_Wcrh, *p_Wckh, *p_Wcvh;
    cudaGetSymbolAddress((void**)&p_xln,  g_xln);
    cudaGetSymbolAddress((void**)&p_k,    g_k);
    cudaGetSymbolAddress((void**)&p_v,    g_v);
    cudaGetSymbolAddress((void**)&p_r,    g_r);
    cudaGetSymbolAddress((void**)&p_xmid, g_xmid);
    cudaGetSymbolAddress((void**)&p_cr,   g_cr);
    cudaGetSymbolAddress((void**)&p_xph,  g_xph);
    cudaGetSymbolAddress((void**)&p_xpl,  g_xpl);
    cudaGetSymbolAddress((void**)&p_x2h,  g_x2h);
    cudaGetSymbolAddress((void**)&p_x2l,  g_x2l);
    cudaGetSymbolAddress((void**)&p_Hh,   g_Hh);
    cudaGetSymbolAddress((void**)&p_Hl,   g_Hl);
    cudaGetSymbolAddress((void**)&p_Wkh,  g_Wkh);
    cudaGetSymbolAddress((void**)&p_Wvh,  g_Wvh);
    cudaGetSymbolAddress((void**)&p_Wrh,  g_Wrh);
    cudaGetSymbolAddress((void**)&p_Wcrh, g_Wcrh);
    cudaGetSymbolAddress((void**)&p_Wckh, g_Wckh);
    cudaGetSymbolAddress((void**)&p_Wcvh, g_Wcvh);

    cudaFuncSetAttribute(hmma_gemm<0>, cudaFuncAttributeMaxDynamicSharedMemorySize, SMEM_BYTES);
    cudaFuncSetAttribute(hmma_gemm<1>, cudaFuncAttributeMaxDynamicSharedMemorySize, SMEM_BYTES);
    cudaFuncSetAttribute(hmma_gemm<2>, cudaFuncAttributeMaxDynamicSharedMemorySize, SMEM_BYTES);
    cudaFuncSetAttribute(hmma_gemm<3>, cudaFuncAttributeMaxDynamicSharedMemorySize, SMEM_BYTES);

    // weight conversion: fp16 hi plane only
    conv_h<<<(CC*CC)/1024,  256>>>((const float4*)Wk,  (uint2*)p_Wkh);
    conv_h<<<(CC*CC)/1024,  256>>>((const float4*)Wv,  (uint2*)p_Wvh);
    conv_h<<<(CC*CC)/1024,  256>>>((const float4*)Wr,  (uint2*)p_Wrh);
    conv_h<<<(CC*CC)/1024,  256>>>((const float4*)Wcr, (uint2*)p_Wcrh);
    conv_h<<<(FFD*CC)/1024, 256>>>((const float4*)Wck, (uint2*)p_Wckh);
    conv_h<<<(CC*FFD)/1024, 256>>>((const float4*)Wcv, (uint2*)p_Wcvh);

    // LN1 -> xln fp32 + padded fp16 planes (row m stored at plane row m+1)
    ln_kernel<<<BT, 256>>>(x, ln1_g, ln1_b, p_xln, p_xph + CC, p_xpl + CC);
    zero2<<<CC/256, 256>>>(p_xph, p_xpl);

    if ((size_t)out_size >= (size_t)BT * CC + (size_t)BB * CC)
        state_kernel<<<(BB * CC) / 256, 256>>>(out + (size_t)BT * CC);

    // k, v (shifted planes base), r (unshifted = +CC)
    dim3 gC(CC / 128, BT / 128);
    hmma_gemm<0><<<gC, 256, SMEM_BYTES>>>(p_xph,      p_xpl,      p_Wkh, p_k, 0,0,0,0, CC, CC);
    hmma_gemm<0><<<gC, 256, SMEM_BYTES>>>(p_xph,      p_xpl,      p_Wvh, p_v, 0,0,0,0, CC, CC);
    hmma_gemm<0><<<gC, 256, SMEM_BYTES>>>(p_xph + CC, p_xpl + CC, p_Wrh, p_r, 0,0,0,0, CC, CC);

    // WKV scan + residual -> xmid
    wkv_passA<<<(BB * NCH * CC) / 256, 256>>>(td);
    wkv_passB<<<(BB * CC) / 256, 256>>>(td);
    wkv_passC<<<(BB * NCH * CC) / 256, 256>>>(td, x);

    // LN2 -> x2 planes (fp32 dump reuses g_xln; state already copied)
    ln_kernel<<<BT, 256>>>(p_xmid, ln2_g, ln2_b, p_xln, p_x2h, p_x2l);

    // channel mix
    dim3 gF(FFD / 128, BT / 128);
    hmma_gemm<1><<<gF, 256, SMEM_BYTES>>>(p_x2h, p_x2l, p_Wckh, 0, p_Hh, p_Hl, 0,0, FFD, CC);     // relu^2 -> H planes
    hmma_gemm<2><<<gC, 256, SMEM_BYTES>>>(p_x2h, p_x2l, p_Wcrh, p_cr, 0,0,0,0, CC, CC);           // sigmoid -> cr
    hmma_gemm<3><<<gC, 256, SMEM_BYTES>>>(p_Hh,  p_Hl,  p_Wcvh, out, 0,0, p_xmid, p_cr, CC, FFD); // out = xmid + cr*dv
}

// round 6
// speedup vs baseline: 7.7331x; 1.9469x over previous
#include <cuda_runtime.h>
#include <cuda_fp16.h>
#include <cstdint>

#define BB 4
#define TT 2048
#define CC 2048
#define FFD 8192
#define BT (BB*TT)          // 8192
#define NCH 64
#define LCH 32

// ---------------- scratch (device globals; no allocation allowed) ----------
__device__ float g_xln [(size_t)BT*CC];
__device__ float g_k   [(size_t)BT*CC];
__device__ float g_v   [(size_t)BT*CC];
__device__ float g_r   [(size_t)BT*CC];
__device__ float g_xmid[(size_t)BT*CC];
__device__ float g_cr  [(size_t)BT*CC];
__device__ float g_Aloc[(size_t)BB*CC*NCH];
__device__ float g_Bloc[(size_t)BB*CC*NCH];
__device__ float g_Sa  [(size_t)BB*CC*NCH];
__device__ float g_Sb  [(size_t)BB*CC*NCH];

// fp16 planes (single plane: activations and weights both quantized)
__device__ __half g_xph[((size_t)BT+1)*CC];   // padded: row0 = 0, row m+1 = xln row m
__device__ __half g_x2h[(size_t)BT*CC];
__device__ __half g_Hh [(size_t)BT*FFD];
__device__ __half g_Wkh [(size_t)CC*CC];
__device__ __half g_Wvh [(size_t)CC*CC];
__device__ __half g_Wrh [(size_t)CC*CC];
__device__ __half g_Wcrh[(size_t)CC*CC];
__device__ __half g_Wckh[(size_t)FFD*CC];
__device__ __half g_Wcvh[(size_t)CC*FFD];

// ======================= PTX helpers (compute_80-safe) ======================
__device__ __forceinline__ uint32_t smem_u32(const void* p) {
    uint32_t a;
    asm("{ .reg .u64 t; cvta.to.shared.u64 t, %1; cvt.u32.u64 %0, t; }" : "=r"(a) : "l"(p));
    return a;
}
__device__ __forceinline__ void cp_async16(uint32_t dst, const void* src) {
    asm volatile("cp.async.cg.shared.global [%0], [%1], 16;" :: "r"(dst), "l"(src) : "memory");
}
__device__ __forceinline__ void cp_commit() {
    asm volatile("cp.async.commit_group;" ::: "memory");
}
template <int N>
__device__ __forceinline__ void cp_wait() {
    asm volatile("cp.async.wait_group %0;" :: "n"(N) : "memory");
}
__device__ __forceinline__ void ldm_x4(uint32_t* r, uint32_t addr) {
    asm volatile("ldmatrix.sync.aligned.m8n8.x4.shared.b16 {%0,%1,%2,%3}, [%4];"
        : "=r"(r[0]), "=r"(r[1]), "=r"(r[2]), "=r"(r[3]) : "r"(addr));
}
__device__ __forceinline__ void ldm_x2(uint32_t* r, uint32_t addr) {
    asm volatile("ldmatrix.sync.aligned.m8n8.x2.shared.b16 {%0,%1}, [%2];"
        : "=r"(r[0]), "=r"(r[1]) : "r"(addr));
}
__device__ __forceinline__ void mma_f16(float* d, const uint32_t* a, const uint32_t* b) {
    asm volatile(
        "mma.sync.aligned.m16n8k16.row.col.f32.f16.f16.f32 "
        "{%0,%1,%2,%3}, {%4,%5,%6,%7}, {%8,%9}, {%0,%1,%2,%3};"
        : "+f"(d[0]), "+f"(d[1]), "+f"(d[2]), "+f"(d[3])
        : "r"(a[0]), "r"(a[1]), "r"(a[2]), "r"(a[3]), "r"(b[0]), "r"(b[1]));
}
__device__ __forceinline__ uint32_t pkh(__half a, __half b) {
    return (uint32_t)__half_as_ushort(a) | ((uint32_t)__half_as_ushort(b) << 16);
}

// ======================= HMMA GEMM ==========================================
// Y[M,N] = A[M,K] @ W[N,K]^T, fp16 single plane, 1 MMA per k-step tile.
// BM=128, BN=128, BK=32, 256 threads, 5-stage cp.async pipeline,
// 2 CTAs per SM. Stage s lives in buffer s % NSTAGE.
// Smem per stage: 2 tiles (A, W), each 128 rows x 80B pitch (32 fp16 data).
// EPI: 0 fp32 | 1 relu^2 -> fp16 plane | 2 sigmoid fp32 | 3 out = xadd + xmul*acc
#define ROWB 80u
#define TILEB (128u*ROWB)         // 10240
#define STAGEB (2u*TILEB)         // 20480
#define NSTAGE 5
#define SMEM_BYTES (NSTAGE*STAGEB)  // 102400

template <int EPI>
__global__ __launch_bounds__(256, 2) void hmma_gemm(
    const __half* __restrict__ Ah, const __half* __restrict__ Wh,
    float* __restrict__ out,
    __half* __restrict__ oh,
    const float* __restrict__ xadd, const float* __restrict__ xmul,
    int N, int K)
{
    extern __shared__ char smem[];
    const uint32_t sbase = smem_u32(smem);
    const int tid  = threadIdx.x;
    const int lane = tid & 31;
    const int wid  = tid >> 5;
    const int warp_m = wid & 1;         // 2 warps in M
    const int warp_n = wid >> 1;        // 4 warps in N
    const int m0 = blockIdx.y * 128;
    const int n0 = blockIdx.x * 128;
    const int S = K >> 5;               // K / 32

    // --- loader mapping: 1024 chunks of 16B per stage, 4 per thread ---------
    // idx: tile = idx>>9 (0 A, 1 W), r = (idx>>2)&127, s = idx&3
    const __half* srcBase[2] = { Ah + (size_t)m0 * K, Wh + (size_t)n0 * K };

    auto load_stage = [&](int buf, int i) {
        const int k0 = i << 5;
        const uint32_t stage = sbase + buf * STAGEB;
        #pragma unroll
        for (int rep = 0; rep < 4; rep++) {
            const int idx = tid + rep * 256;
            const int tile = idx >> 9;
            const int r = (idx >> 2) & 127;
            const int s = idx & 3;
            const __half* src = srcBase[tile] + (size_t)r * K + k0 + s * 8;
            cp_async16(stage + tile * TILEB + r * ROWB + s * 16, src);
        }
    };

    // prologue: stages 0..NSTAGE-2
    #pragma unroll
    for (int p = 0; p < NSTAGE - 1; p++) { load_stage(p, p); cp_commit(); }

    float acc[4][4][4];
    #pragma unroll
    for (int mt = 0; mt < 4; mt++)
        #pragma unroll
        for (int nt = 0; nt < 4; nt++)
            #pragma unroll
            for (int q = 0; q < 4; q++) acc[mt][nt][q] = 0.f;

    // ldmatrix per-lane offsets (bytes)
    const uint32_t aoff = (lane & 15) * ROWB + (lane >> 4) * 16;
    const uint32_t boff = (lane & 7) * ROWB + ((lane >> 3) & 1) * 16;

    for (int i = 0; i < S; i++) {
        cp_wait<NSTAGE - 2>();      // stage i resident
        __syncthreads();
        const uint32_t sb = sbase + (i % NSTAGE) * STAGEB;
        #pragma unroll
        for (int ks = 0; ks < 2; ks++) {
            const uint32_t kb = ks * 32;   // 16 cols * 2B
            uint32_t ahf[4][4];
            #pragma unroll
            for (int mt = 0; mt < 4; mt++)
                ldm_x4(ahf[mt], sb + (warp_m * 64 + mt * 16) * ROWB + kb + aoff);
            uint32_t bhf[4][2];
            #pragma unroll
            for (int nt = 0; nt < 4; nt++)
                ldm_x2(bhf[nt], sb + TILEB + (warp_n * 32 + nt * 8) * ROWB + kb + boff);
            #pragma unroll
            for (int mt = 0; mt < 4; mt++)
                #pragma unroll
                for (int nt = 0; nt < 4; nt++)
                    mma_f16(acc[mt][nt], ahf[mt], bhf[nt]);
        }
        // refill buffer (i+NSTAGE-1)%NSTAGE == (i-1)%NSTAGE: consumed at i-1,
        // all warps are past it via this iteration's entry barrier.
        if (i + NSTAGE - 1 < S) load_stage((i + NSTAGE - 1) % NSTAGE, i + NSTAGE - 1);
        cp_commit();
    }

    // ---------------- epilogue --------------------------------------------
    const int rbase = m0 + warp_m * 64 + (lane >> 2);
    const int cbase = n0 + warp_n * 32 + (lane & 3) * 2;
    #pragma unroll
    for (int mt = 0; mt < 4; mt++) {
        #pragma unroll
        for (int nt = 0; nt < 4; nt++) {
            const float* c = acc[mt][nt];
            const size_t r0 = (size_t)(rbase + mt * 16);
            const size_t r1 = r0 + 8;
            const int col = cbase + nt * 8;
            if (EPI == 0) {
                *(float2*)&out[r0 * N + col] = make_float2(c[0], c[1]);
                *(float2*)&out[r1 * N + col] = make_float2(c[2], c[3]);
            } else if (EPI == 2) {
                *(float2*)&out[r0 * N + col] = make_float2(
                    1.f / (1.f + __expf(-c[0])), 1.f / (1.f + __expf(-c[1])));
                *(float2*)&out[r1 * N + col] = make_float2(
                    1.f / (1.f + __expf(-c[2])), 1.f / (1.f + __expf(-c[3])));
            } else if (EPI == 3) {
                float2 a0 = *(const float2*)&xadd[r0 * N + col];
                float2 m0v = *(const float2*)&xmul[r0 * N + col];
                float2 a1 = *(const float2*)&xadd[r1 * N + col];
                float2 m1v = *(const float2*)&xmul[r1 * N + col];
                *(float2*)&out[r0 * N + col] = make_float2(
                    a0.x + m0v.x * c[0], a0.y + m0v.y * c[1]);
                *(float2*)&out[r1 * N + col] = make_float2(
                    a1.x + m1v.x * c[2], a1.y + m1v.y * c[3]);
            } else {  // EPI == 1: relu^2 -> fp16 plane
                float f0 = c[0] > 0.f ? c[0] * c[0] : 0.f;
                float f1 = c[1] > 0.f ? c[1] * c[1] : 0.f;
                float f2 = c[2] > 0.f ? c[2] * c[2] : 0.f;
                float f3 = c[3] > 0.f ? c[3] * c[3] : 0.f;
                *(uint32_t*)&oh[r0 * N + col] = pkh(__float2half_rn(f0), __float2half_rn(f1));
                *(uint32_t*)&oh[r1 * N + col] = pkh(__float2half_rn(f2), __float2half_rn(f3));
            }
        }
    }
}

// ======================= layernorm (+ fp16 plane) ===========================
__device__ __forceinline__ void blockReduce2(float& a, float& b) {
    __shared__ float sa[8], sb[8];
    int lane = threadIdx.x & 31, w = threadIdx.x >> 5;
    #pragma unroll
    for (int o = 16; o > 0; o >>= 1) {
        a += __shfl_down_sync(0xffffffffu, a, o);
        b += __shfl_down_sync(0xffffffffu, b, o);
    }
    if (lane == 0) { sa[w] = a; sb[w] = b; }
    __syncthreads();
    if (w == 0) {
        a = (lane < 8) ? sa[lane] : 0.f;
        b = (lane < 8) ? sb[lane] : 0.f;
        #pragma unroll
        for (int o = 4; o > 0; o >>= 1) {
            a += __shfl_down_sync(0xffffffffu, a, o);
            b += __shfl_down_sync(0xffffffffu, b, o);
        }
        if (lane == 0) { sa[0] = a; sb[0] = b; }
    }
    __syncthreads();
    a = sa[0]; b = sb[0];
    __syncthreads();
}

__global__ __launch_bounds__(256) void ln_kernel(
    const float* __restrict__ x, const float* __restrict__ g,
    const float* __restrict__ bia, float* __restrict__ y,
    __half* __restrict__ yh)
{
    size_t row = blockIdx.x;
    const float* xr = x + row * CC;
    float s = 0.f, q = 0.f;
    for (int i = threadIdx.x; i < CC; i += 256) {
        float v = xr[i];
        s += v; q += v * v;
    }
    blockReduce2(s, q);
    float mu = s * (1.f / CC);
    float var = q * (1.f / CC) - mu * mu;
    float rstd = rsqrtf(var + 1e-5f);
    for (int i = threadIdx.x; i < CC; i += 256) {
        float v = (xr[i] - mu) * rstd * g[i] + bia[i];
        y[row * CC + i] = v;
        yh[row * CC + i] = __float2half_rn(v);
    }
}

// ======================= converters / misc ==================================
__global__ __launch_bounds__(256) void conv_h(
    const float4* __restrict__ src, uint2* __restrict__ hi)
{
    size_t i = (size_t)blockIdx.x * 256 + threadIdx.x;
    float4 f = src[i];
    hi[i] = make_uint2(pkh(__float2half_rn(f.x), __float2half_rn(f.y)),
                       pkh(__float2half_rn(f.z), __float2half_rn(f.w)));
}

__global__ __launch_bounds__(256) void zero1(__half* a)
{
    int i = blockIdx.x * 256 + threadIdx.x;
    a[i] = __float2half_rn(0.f);
}

// ======================= WKV chunked scan ===================================
__global__ __launch_bounds__(256) void wkv_passA(const float* __restrict__ td)
{
    int tid = blockIdx.x * 256 + threadIdx.x;
    int c = tid % CC;
    int j = (tid / CC) % NCH;
    int b = tid / (CC * NCH);
    float d = __expf(-__expf(td[c]));
    float a = 0.f, bb = 0.f;
    size_t base = ((size_t)b * TT + (size_t)j * LCH) * CC + c;
    for (int t = 0; t < LCH; t++) {
        float ek = __expf(g_k[base + (size_t)t * CC]);
        float vv = g_v[base + (size_t)t * CC];
        if (j == 0 && t == 0) { ek = 1.f; vv = 0.f; }   // t_global==0: shifted row is 0
        a  = d * a  + ek * vv;
        bb = d * bb + ek;
    }
    size_t idx = ((size_t)b * NCH + j) * CC + c;
    g_Aloc[idx] = a;
    g_Bloc[idx] = bb;
}

__global__ __launch_bounds__(256) void wkv_passB(const float* __restrict__ td)
{
    int tid = blockIdx.x * 256 + threadIdx.x;
    int c = tid % CC;
    int b = tid / CC;
    float dL = __expf(-(float)LCH * __expf(td[c]));
    float sa = 0.f, sb = 0.f;
    for (int j = 0; j < NCH; j++) {
        size_t idx = ((size_t)b * NCH + j) * CC + c;
        g_Sa[idx] = sa;
        g_Sb[idx] = sb;
        sa = dL * sa + g_Aloc[idx];
        sb = dL * sb + g_Bloc[idx];
    }
}

__global__ __launch_bounds__(256) void wkv_passC(
    const float* __restrict__ td, const float* __restrict__ x)
{
    int tid = blockIdx.x * 256 + threadIdx.x;
    int c = tid % CC;
    int j = (tid / CC) % NCH;
    int b = tid / (CC * NCH);
    float d = __expf(-__expf(td[c]));
    size_t idx = ((size_t)b * NCH + j) * CC + c;
    float a = g_Sa[idx], bb = g_Sb[idx];
    size_t base = ((size_t)b * TT + (size_t)j * LCH) * CC + c;
    for (int t = 0; t < LCH; t++) {
        size_t p = base + (size_t)t * CC;
        float ek = __expf(g_k[p]);
        float vv = g_v[p];
        if (j == 0 && t == 0) { ek = 1.f; vv = 0.f; }
        a  = d * a  + ek * vv;
        bb = d * bb + ek;
        g_xmid[p] = x[p] + g_r[p] * (a / (bb + 1e-8f));
    }
}

__global__ __launch_bounds__(256) void state_kernel(float* __restrict__ out)
{
    int tid = blockIdx.x * 256 + threadIdx.x;
    int c = tid % CC;
    int b = tid / CC;
    out[tid] = g_xln[((size_t)b * TT + (TT - 2)) * CC + c];
}

// ======================= host launch =========================================
extern "C" void kernel_launch(void* const* d_in, const int* in_sizes, int n_in,
                              void* d_out, int out_size)
{
    const float* x     = (const float*)d_in[0];
    const float* ln1_g = (const float*)d_in[1];
    const float* ln1_b = (const float*)d_in[2];
    const float* td    = (const float*)d_in[3];
    const float* Wk    = (const float*)d_in[4];
    const float* Wv    = (const float*)d_in[5];
    const float* Wr    = (const float*)d_in[6];
    const float* ln2_g = (const float*)d_in[7];
    const float* ln2_b = (const float*)d_in[8];
    const float* Wck   = (const float*)d_in[9];
    const float* Wcv   = (const float*)d_in[10];
    const float* Wcr   = (const float*)d_in[11];
    float* out = (float*)d_out;

    float *p_xln, *p_k, *p_v, *p_r, *p_xmid, *p_cr;
    __half *p_xph, *p_x2h, *p_Hh;
    __half *p_Wkh, *p_Wvh, *p_Wrh, *p_Wcrh, *p_Wckh, *p_Wcvh;
    cudaGetSymbolAddress((void**)&p_xln,  g_xln);
    cudaGetSymbolAddress((void**)&p_k,    g_k);
    cudaGetSymbolAddress((void**)&p_v,    g_v);
    cudaGetSymbolAddress((void**)&p_r,    g_r);
    cudaGetSymbolAddress((void**)&p_xmid, g_xmid);
    cudaGetSymbolAddress((void**)&p_cr,   g_cr);
    cudaGetSymbolAddress((void**)&p_xph,  g_xph);
    cudaGetSymbolAddress((void**)&p_x2h,  g_x2h);
    cudaGetSymbolAddress((void**)&p_Hh,   g_Hh);
    cudaGetSymbolAddress((void**)&p_Wkh,  g_Wkh);
    cudaGetSymbolAddress((void**)&p_Wvh,  g_Wvh);
    cudaGetSymbolAddress((void**)&p_Wrh,  g_Wrh);
    cudaGetSymbolAddress((void**)&p_Wcrh, g_Wcrh);
    cudaGetSymbolAddress((void**)&p_Wckh, g_Wckh);
    cudaGetSymbolAddress((void**)&p_Wcvh, g_Wcvh);

    cudaFuncSetAttribute(hmma_gemm<0>, cudaFuncAttributeMaxDynamicSharedMemorySize, SMEM_BYTES);
    cudaFuncSetAttribute(hmma_gemm<1>, cudaFuncAttributeMaxDynamicSharedMemorySize, SMEM_BYTES);
    cudaFuncSetAttribute(hmma_gemm<2>, cudaFuncAttributeMaxDynamicSharedMemorySize, SMEM_BYTES);
    cudaFuncSetAttribute(hmma_gemm<3>, cudaFuncAttributeMaxDynamicSharedMemorySize, SMEM_BYTES);

    // weight conversion: fp16 plane
    conv_h<<<(CC*CC)/1024,  256>>>((const float4*)Wk,  (uint2*)p_Wkh);
    conv_h<<<(CC*CC)/1024,  256>>>((const float4*)Wv,  (uint2*)p_Wvh);
    conv_h<<<(CC*CC)/1024,  256>>>((const float4*)Wr,  (uint2*)p_Wrh);
    conv_h<<<(CC*CC)/1024,  256>>>((const float4*)Wcr, (uint2*)p_Wcrh);
    conv_h<<<(FFD*CC)/1024, 256>>>((const float4*)Wck, (uint2*)p_Wckh);
    conv_h<<<(CC*FFD)/1024, 256>>>((const float4*)Wcv, (uint2*)p_Wcvh);

    // LN1 -> xln fp32 + padded fp16 plane (row m stored at plane row m+1)
    ln_kernel<<<BT, 256>>>(x, ln1_g, ln1_b, p_xln, p_xph + CC);
    zero1<<<CC/256, 256>>>(p_xph);

    if ((size_t)out_size >= (size_t)BT * CC + (size_t)BB * CC)
        state_kernel<<<(BB * CC) / 256, 256>>>(out + (size_t)BT * CC);

    // k, v (shifted plane base), r (unshifted = +CC)
    dim3 gC(CC / 128, BT / 128);
    hmma_gemm<0><<<gC, 256, SMEM_BYTES>>>(p_xph,      p_Wkh, p_k, 0, 0, 0, CC, CC);
    hmma_gemm<0><<<gC, 256, SMEM_BYTES>>>(p_xph,      p_Wvh, p_v, 0, 0, 0, CC, CC);
    hmma_gemm<0><<<gC, 256, SMEM_BYTES>>>(p_xph + CC, p_Wrh, p_r, 0, 0, 0, CC, CC);

    // WKV scan + residual -> xmid
    wkv_passA<<<(BB * NCH * CC) / 256, 256>>>(td);
    wkv_passB<<<(BB * CC) / 256, 256>>>(td);
    wkv_passC<<<(BB * NCH * CC) / 256, 256>>>(td, x);

    // LN2 -> x2 plane (fp32 dump reuses g_xln; state already copied)
    ln_kernel<<<BT, 256>>>(p_xmid, ln2_g, ln2_b, p_xln, p_x2h);

    // channel mix
    dim3 gF(FFD / 128, BT / 128);
    hmma_gemm<1><<<gF, 256, SMEM_BYTES>>>(p_x2h, p_Wckh, 0, p_Hh, 0, 0, FFD, CC);          // relu^2 -> H plane
    hmma_gemm<2><<<gC, 256, SMEM_BYTES>>>(p_x2h, p_Wcrh, p_cr, 0, 0, 0, CC, CC);           // sigmoid -> cr
    hmma_gemm<3><<<gC, 256, SMEM_BYTES>>>(p_Hh,  p_Wcvh, out, 0, p_xmid, p_cr, CC, FFD);   // out = xmid + cr*dv
}